// round 15
// baseline (speedup 1.0000x reference)
#include <cuda_runtime.h>
#include <cuda_fp16.h>
#include <math.h>

#define T_LEN  (1 << 20)
#define CPT    32                  // elements per thread
#define BLK    128
#define NWARP  (BLK / 32)          // 4
#define CHUNK  (BLK * CPT)         // 4096 (unchanged)
#define NCHUNK (T_LEN / CHUNK)     // 256
#define NB     4
#define HMIN   6.103515625e-05f    // fp16 min normal clip floor (validated: rel_err 4.4e-5)
#define NBLOCKS (NB * NCHUNK)
// Hardcoded shifts: int(44100*(l_ms-s_ms)*0.0005)
#define SH0 10804
#define SH1 31972
#define SH2 63945

struct Consts {
    float a[6];    // 1 - c   (k 0..2 short, 3..5 long)
    float aC[6];   // a^CPT (= a^32)
    float aL[6];   // a^CHUNK (up to 0.934 for tau=3000ms -> FULL lookback required)
    float aL128[6];// aL^128 (for second lookback element per thread)
};

// Static device scratch (no cudaMalloc allowed)
__device__ __align__(128) float g_tot[NB][NCHUNK][32];   // chunk-local totals (24 used)
__device__ int      g_flag[NB][NCHUNK];                  // totals published
__device__ int      g_cflag[NB][3][NCHUNK];              // C-chunk write counters (==2 when ready)
// half2 (row0,row1) streams: [b][i][kind 0=A(short; only i=2 used) 1=C(long,pre-shifted)][addr]
__device__ __align__(16) unsigned g_S[NB][3][2][T_LEN];
__device__ float    g_part[NBLOCKS];
__device__ unsigned g_done;

__device__ __forceinline__ int ld_acquire(const int* p) {
    int v;
    asm volatile("ld.acquire.gpu.b32 %0, [%1];" : "=r"(v) : "l"(p) : "memory");
    return v;
}
__device__ __forceinline__ void st_release(int* p, int v) {
    asm volatile("st.release.gpu.b32 [%0], %1;" :: "l"(p), "r"(v) : "memory");
}
__device__ __forceinline__ unsigned h2u(__half2 h) {
    return *reinterpret_cast<const unsigned*>(&h);
}
__device__ __forceinline__ float2 u2f2(unsigned u) {
    return __half22float2(*reinterpret_cast<const __half2*>(&u));
}
// Within-chunk transpose: t = g*4096 + tid*32 + el  ->  addr = g*4096 + el*128 + tid.
__device__ __forceinline__ int amap(int s) {
    return (s & ~4095) | ((s & 31) << 7) | ((s & 4095) >> 5);
}

// out[k] = base[k]^e via exact squaring ladder (e <= 255)
__device__ __forceinline__ void pow_ladder(float* out, const float* base, int e) {
#pragma unroll
    for (int k = 0; k < 6; k++) {
        float p = 1.0f, bb = base[k];
        int ee = e;
#pragma unroll
        for (int bit = 0; bit < 8; bit++) { if (ee & 1) p *= bb; bb *= bb; ee >>= 1; }
        out[k] = p;
    }
}

// 24 z-chains (c factored out; cancels in log-differences):
// z[0..5]=pred-mid, z[6..11]=true-mid, z[12..17]=pred-side, z[18..23]=true-side
__device__ __forceinline__ void chain24(float* z, const Consts& K,
                                        float vpm, float vtm, float vps, float vts) {
#pragma unroll
    for (int k = 0; k < 6; k++) {
        z[k]      = fmaf(K.a[k], z[k],      vpm);
        z[6 + k]  = fmaf(K.a[k], z[6 + k],  vtm);
        z[12 + k] = fmaf(K.a[k], z[12 + k], vps);
        z[18 + k] = fmaf(K.a[k], z[18 + k], vts);
    }
}

__global__ __launch_bounds__(BLK, 6) void fused_kernel(const float* __restrict__ xp,
                                                       const float* __restrict__ xt, Consts K,
                                                       float* __restrict__ out) {
    // fp16x2 v-cache (32KB): [kind][el][tid]; phase C overwrites consumed slots with
    // A(i=0,1); tail reads them back via LDS. A(i=2) + all C go through global.
    __shared__ __align__(16) unsigned sv[2 * CPT * BLK];
    __shared__ float wagg[24][NWARP];             // exclusive warp prefixes
    __shared__ float cagg[24][NWARP];             // lookback cross-warp partials
    __shared__ __align__(16) float tot_s[24];     // block totals
    __shared__ float cb_s[24];                    // chunk carry-in
    __shared__ float red[BLK];
    __shared__ bool  last;

    int g = blockIdx.x, b = blockIdx.y, tid = threadIdx.x;
    int lane = tid & 31, warp = tid >> 5;
    size_t base = (size_t)g * CHUNK + (size_t)tid * CPT;
    const float4* p0 = (const float4*)(xp + (size_t)(b * 2 + 0) * T_LEN + base);
    const float4* p1 = (const float4*)(xp + (size_t)(b * 2 + 1) * T_LEN + base);
    const float4* q0 = (const float4*)(xt + (size_t)(b * 2 + 0) * T_LEN + base);
    const float4* q1 = (const float4*)(xt + (size_t)(b * 2 + 1) * T_LEN + base);

    // ── Phase A: read input ONCE, quantize v to half2 (cached in smem), run 24 chains ──
    float y[24];
#pragma unroll
    for (int c = 0; c < 24; c++) y[c] = 0.0f;

#pragma unroll
    for (int jj = 0; jj < CPT / 4; jj++) {
        float4 a0 = p0[jj], a1 = p1[jj], b0 = q0[jj], b1 = q1[jj];
#define PH_A(e, el) {                                                            \
        float sm = a0.e + a1.e, sd = a0.e - a1.e;                                \
        float tm = b0.e + b1.e, td = b0.e - b1.e;                                \
        __half2 va = __floats2half2_rn(fmaxf(0.5f * sm * sm, HMIN),              \
                                       fmaxf(0.5f * tm * tm, HMIN));             \
        __half2 vb = __floats2half2_rn(fmaxf(0.5f * sd * sd, HMIN),              \
                                       fmaxf(0.5f * td * td, HMIN));             \
        sv[(el) * BLK + tid] = h2u(va);                                          \
        sv[CPT * BLK + (el) * BLK + tid] = h2u(vb);                              \
        float2 fa = __half22float2(va), fb = __half22float2(vb);                 \
        chain24(y, K, fa.x, fa.y, fb.x, fb.y); }
        PH_A(x, jj * 4 + 0) PH_A(y, jj * 4 + 1) PH_A(z, jj * 4 + 2) PH_A(w, jj * 4 + 3)
#undef PH_A
    }

    // ── Warp decayed scan over 24 channels ──
    float pw[6];
#pragma unroll
    for (int k = 0; k < 6; k++) pw[k] = K.aC[k];
#pragma unroll
    for (int off = 1; off < 32; off <<= 1) {
#pragma unroll
        for (int c = 0; c < 24; c++) {
            float up = __shfl_up_sync(0xffffffffu, y[c], off);
            if (lane >= off) y[c] = fmaf(pw[c % 6], up, y[c]);
        }
#pragma unroll
        for (int k = 0; k < 6; k++) pw[k] *= pw[k];   // ends at aC^32
    }
    if (lane == 31) {
#pragma unroll
        for (int c = 0; c < 24; c++) wagg[c][warp] = y[c];
    }
    __syncthreads();
    if (tid < 24) {
        float p = 0.0f, aW = pw[tid % 6];
#pragma unroll
        for (int w = 0; w < NWARP; w++) {
            float t = wagg[tid][w];
            wagg[tid][w] = p;               // exclusive warp prefix
            p = fmaf(aW, p, t);
        }
        tot_s[tid] = p;                     // block total
    }
    __syncthreads();

    // ── Publish local totals ASAP (before any waiting!) ──
    if (tid == 0) {
        float4* dst = (float4*)g_tot[b][g];
#pragma unroll
        for (int q = 0; q < 6; q++) dst[q] = ((float4*)tot_s)[q];
        st_release(&g_flag[b][g], 1);
    }

    // ── Thread-exclusive local prefix (block scope) ──
    float cin[24];
    {
        float alane[6];
        pow_ladder(alane, K.aC, lane + 1);
#pragma unroll
        for (int c = 0; c < 24; c++) {
            float P  = wagg[c][warp];
            float bi = fmaf(alane[c % 6], P, y[c]);        // block-inclusive
            float pr = __shfl_up_sync(0xffffffffu, bi, 1);
            cin[c] = (lane == 0) ? P : pr;
        }
    }

    // ── Phase B: FULL decoupled lookback (2 predecessors per thread: depth 256) ──
    float contrib[24];
#pragma unroll
    for (int c = 0; c < 24; c++) contrib[c] = 0.0f;
    if (tid < g) {
        int j = g - 1 - tid;
        float wd[6];
        pow_ladder(wd, K.aL, tid);
        while (!ld_acquire(&g_flag[b][j])) __nanosleep(64);
        const float4* tp = (const float4*)g_tot[b][j];
#pragma unroll
        for (int q = 0; q < 6; q++) {
            float4 v4 = __ldcg(tp + q);
            contrib[q * 4 + 0] = wd[(q * 4 + 0) % 6] * v4.x;
            contrib[q * 4 + 1] = wd[(q * 4 + 1) % 6] * v4.y;
            contrib[q * 4 + 2] = wd[(q * 4 + 2) % 6] * v4.z;
            contrib[q * 4 + 3] = wd[(q * 4 + 3) % 6] * v4.w;
        }
        int j2 = j - BLK;
        if (j2 >= 0) {
            float wd2[6];
#pragma unroll
            for (int k = 0; k < 6; k++) wd2[k] = wd[k] * K.aL128[k];
            while (!ld_acquire(&g_flag[b][j2])) __nanosleep(64);
            const float4* tp2 = (const float4*)g_tot[b][j2];
#pragma unroll
            for (int q = 0; q < 6; q++) {
                float4 v4 = __ldcg(tp2 + q);
                contrib[q * 4 + 0] = fmaf(wd2[(q * 4 + 0) % 6], v4.x, contrib[q * 4 + 0]);
                contrib[q * 4 + 1] = fmaf(wd2[(q * 4 + 1) % 6], v4.y, contrib[q * 4 + 1]);
                contrib[q * 4 + 2] = fmaf(wd2[(q * 4 + 2) % 6], v4.z, contrib[q * 4 + 2]);
                contrib[q * 4 + 3] = fmaf(wd2[(q * 4 + 3) % 6], v4.w, contrib[q * 4 + 3]);
            }
        }
    }
#pragma unroll
    for (int off = 16; off > 0; off >>= 1) {
#pragma unroll
        for (int c = 0; c < 24; c++)
            contrib[c] += __shfl_xor_sync(0xffffffffu, contrib[c], off);
    }
    if (lane == 0) {
#pragma unroll
        for (int c = 0; c < 24; c++) cagg[c][warp] = contrib[c];
    }
    __syncthreads();
    if (tid < 24) {
        float s = 0.0f;
#pragma unroll
        for (int w = 0; w < NWARP; w++) s += cagg[tid][w];
        cb_s[tid] = s;
    }
    __syncthreads();

    {   // fold chunk carry into per-thread carry-in: cin += aC^tid * carry
        float atid[6];
        pow_ladder(atid, K.aC, tid);
#pragma unroll
        for (int c = 0; c < 24; c++) cin[c] = fmaf(atid[c % 6], cb_s[c], cin[c]);
    }

    // ── Phase C: replay chains from smem-cached v; A(i=0,1) overwrites v slots in smem,
    //            A(i=2) to global; C pre-shifted to global ──
    int tbase = g * CHUNK + tid * CPT;
    int abase = g * CHUNK + tid;       // amap(t) = g*4096 + el*128 + tid
    const int sh[3] = {SH0, SH1, SH2};

#pragma unroll
    for (int el = 0; el < CPT; el++) {
        float2 fa = u2f2(sv[el * BLK + tid]);
        float2 fb = u2f2(sv[CPT * BLK + el * BLK + tid]);
        chain24(cin, K, fa.x, fa.y, fb.x, fb.y);
        int t = tbase + el;
        int aad = abase + (el << 7);
#pragma unroll
        for (int i = 0; i < 3; i++) {
            __half2 Av = __floats2half2_rn(__log2f(cin[i])      - __log2f(cin[6 + i]),
                                           __log2f(cin[12 + i]) - __log2f(cin[18 + i]));
            __half2 Cv = __floats2half2_rn(__log2f(cin[3 + i])  - __log2f(cin[9 + i]),
                                           __log2f(cin[15 + i]) - __log2f(cin[21 + i]));
            if (i < 2) sv[i * (CPT * BLK) + el * BLK + tid] = h2u(Av);   // smem A cache
            else       g_S[b][2][0][aad] = h2u(Av);
            int t2 = (t - sh[i]) & (T_LEN - 1);
            g_S[b][i][1][amap(t2)] = h2u(Cv);
        }
    }

    // ── Arrive on the C chunks this block wrote (after ALL stores) ──
    __syncthreads();
    if (tid < 6) {
        __threadfence();
        int i = tid >> 1;
        const int FO[3] = {2, 7, 15};           // floor(sh/4096)
        int c = (g - FO[i] - (tid & 1)) & (NCHUNK - 1);
        atomicAdd(&g_cflag[b][i][c], 1);
    }
    // ── Wait for own C chunk (writers arrive before their own waits -> progress) ──
    if (tid < 3) {
        while (ld_acquire(&g_cflag[b][tid][g]) < 2) __nanosleep(64);
    }
    __syncthreads();

    // ── Tail: reduce |A - C| over own chunk. A(i=0,1) from smem, rest global (L2-hot) ──
    float acc = 0.0f;
    int base4 = g * (CHUNK / 4);                 // uint4 index of chunk start
#pragma unroll
    for (int i = 0; i < 3; i++) {
        const uint4* C4 = (const uint4*)&g_S[b][i][1][0];
        const uint4* A4 = (const uint4*)&g_S[b][2][0][0];   // used only when i==2
#pragma unroll
        for (int r = 0; r < CHUNK / 4 / BLK; r++) {          // 8 iterations
            int lin = r * BLK + tid;                         // uint4 index within chunk
            uint4 a;
            if (i < 2) {
                a = *(const uint4*)&sv[i * (CPT * BLK) + 4 * lin];  // LDS.128
            } else {
                a = __ldcg(A4 + base4 + lin);
            }
            uint4 c = __ldcg(C4 + base4 + lin);
            const __half2* ha = (const __half2*)&a;
            const __half2* hc = (const __half2*)&c;
#pragma unroll
            for (int q = 0; q < 4; q++) {
                __half2 d = __habs2(__hsub2(ha[q], hc[q]));
                float2 fl = __half22float2(d);
                acc += fl.x + fl.y;
            }
        }
    }
    red[tid] = acc;
    __syncthreads();
    for (int s = BLK / 2; s > 0; s >>= 1) {
        if (tid < s) red[tid] += red[tid + s];
        __syncthreads();
    }
    int bid = b * NCHUNK + g;
    if (tid == 0) {
        g_part[bid] = red[0];
        __threadfence();
        unsigned old = atomicAdd(&g_done, 1u);
        last = (old == NBLOCKS - 1);
    }
    __syncthreads();

    // ── Last block: deterministic final reduction + state reset for next replay ──
    if (last) {
        __threadfence();
        float v = 0.0f;
        for (int idx = tid; idx < NBLOCKS; idx += BLK) v += __ldcg(&g_part[idx]);
        red[tid] = v;
        __syncthreads();
        for (int s = BLK / 2; s > 0; s >>= 1) {
            if (tid < s) red[tid] += red[tid + s];
            __syncthreads();
        }
        if (tid == 0) {
            out[0] = (float)((double)red[0] * 0.69314718055994530942 / (8.0 * (double)T_LEN));
            g_done = 0;
        }
        for (int idx = tid; idx < NB * NCHUNK; idx += BLK) ((int*)g_flag)[idx] = 0;
        for (int idx = tid; idx < NB * 3 * NCHUNK; idx += BLK) ((int*)g_cflag)[idx] = 0;
    }
}

extern "C" void kernel_launch(void* const* d_in, const int* in_sizes, int n_in,
                              void* d_out, int out_size) {
    const float* xp = (const float*)d_in[0];
    const float* xt = (const float*)d_in[1];
    (void)in_sizes; (void)n_in; (void)out_size;

    static bool attr_set = false;
    if (!attr_set) {
        cudaFuncSetAttribute(fused_kernel,
                             cudaFuncAttributePreferredSharedMemoryCarveout,
                             cudaSharedmemCarveoutMaxShared);
        attr_set = true;
    }

    Consts K;
    const double sr = 44100.0;
    const double s_taus[3] = {10.0, 50.0, 100.0};
    const double l_taus[3] = {500.0, 1500.0, 3000.0};
    float cco[6];
    for (int i = 0; i < 3; i++) {
        cco[i]     = (float)(1.0 - exp(-2200.0 / (s_taus[i] * sr)));
        cco[3 + i] = (float)(1.0 - exp(-2200.0 / (l_taus[i] * sr)));
    }
    for (int k = 0; k < 6; k++) {
        K.a[k]     = 1.0f - cco[k];
        K.aC[k]    = (float)pow((double)K.a[k], (double)CPT);
        K.aL[k]    = (float)pow((double)K.a[k], (double)CHUNK);
        K.aL128[k] = (float)pow((double)K.aL[k], 128.0);
    }

    dim3 grid(NCHUNK, NB);
    fused_kernel<<<grid, BLK>>>(xp, xt, K, (float*)d_out);
}

// round 16
// speedup vs baseline: 1.3734x; 1.3734x over previous
#include <cuda_runtime.h>
#include <cuda_fp16.h>
#include <math.h>

#define T_LEN  (1 << 20)
#define CPT    16                  // elements per thread
#define BLK    256
#define CHUNK  (BLK * CPT)         // 4096
#define NCHUNK (T_LEN / CHUNK)     // 256
#define NB     4
#define HMIN   6.103515625e-05f    // fp16 min normal clip floor (validated: rel_err 4.4e-5)
#define NBLOCKS (NB * NCHUNK)
// Hardcoded shifts: int(44100*(l_ms-s_ms)*0.0005)
#define SH0 10804
#define SH1 31972
#define SH2 63945

struct Consts {
    float a[6];   // 1 - c   (k 0..2 short, 3..5 long)
    float aC[6];  // a^CPT
    float aL[6];  // a^CHUNK (up to 0.934 for tau=3000ms -> FULL lookback required)
};

// Static device scratch (no cudaMalloc allowed)
__device__ __align__(128) float g_tot[NB][NCHUNK][32];   // chunk-local totals (24 used)
__device__ int      g_flag[NB][NCHUNK];                  // totals published
__device__ int      g_cflag[NB][3][NCHUNK];              // A-chunk write counters (==2 when ready)
// half2 (row0,row1) streams: [b][i][kind 0=A(short, pre-shifted FORWARD) 1=C(long, own addr; only i=2)]
__device__ __align__(16) unsigned g_S[NB][3][2][T_LEN];
__device__ float    g_part[NBLOCKS];
__device__ unsigned g_done;

__device__ __forceinline__ int ld_acquire(const int* p) {
    int v;
    asm volatile("ld.acquire.gpu.b32 %0, [%1];" : "=r"(v) : "l"(p) : "memory");
    return v;
}
__device__ __forceinline__ void st_release(int* p, int v) {
    asm volatile("st.release.gpu.b32 [%0], %1;" :: "l"(p), "r"(v) : "memory");
}
__device__ __forceinline__ unsigned h2u(__half2 h) {
    return *reinterpret_cast<const unsigned*>(&h);
}
__device__ __forceinline__ float2 u2f2(unsigned u) {
    return __half22float2(*reinterpret_cast<const __half2*>(&u));
}
// Within-chunk transpose: amap(t) for t = g*4096 + tid*16 + el is g*4096 + el*256 + tid.
__device__ __forceinline__ int amap(int s) {
    return (s & ~4095) | ((s & 15) << 8) | ((s & 4095) >> 4);
}

// out[k] = base[k]^e via exact squaring ladder (e <= 255)
__device__ __forceinline__ void pow_ladder(float* out, const float* base, int e) {
#pragma unroll
    for (int k = 0; k < 6; k++) {
        float p = 1.0f, bb = base[k];
        int ee = e;
#pragma unroll
        for (int bit = 0; bit < 8; bit++) { if (ee & 1) p *= bb; bb *= bb; ee >>= 1; }
        out[k] = p;
    }
}

// 24 z-chains (c factored out; cancels in log-differences):
// z[0..5]=pred-mid, z[6..11]=true-mid, z[12..17]=pred-side, z[18..23]=true-side
__device__ __forceinline__ void chain24(float* z, const Consts& K,
                                        float vpm, float vtm, float vps, float vts) {
#pragma unroll
    for (int k = 0; k < 6; k++) {
        z[k]      = fmaf(K.a[k], z[k],      vpm);
        z[6 + k]  = fmaf(K.a[k], z[6 + k],  vtm);
        z[12 + k] = fmaf(K.a[k], z[12 + k], vps);
        z[18 + k] = fmaf(K.a[k], z[18 + k], vts);
    }
}

__global__ __launch_bounds__(BLK, 4) void fused_kernel(const float* __restrict__ xp,
                                                       const float* __restrict__ xt, Consts K,
                                                       float* __restrict__ out) {
    // fp16x2 v-cache (32KB): [kind][el][tid]. Phase C overwrites consumed slots with
    // the LONG (C) log-diff for i = kind (0/1); tail reads them back via LDS.
    // C(i=2) and all pre-shifted A go through global.
    __shared__ __align__(16) unsigned sv[2 * CPT * BLK];
    __shared__ float wagg[24][8];                 // exclusive warp prefixes
    __shared__ float cagg[24][8];                 // lookback cross-warp partials
    __shared__ __align__(16) float tot_s[24];     // block totals
    __shared__ float cb_s[24];                    // chunk carry-in
    __shared__ float red[BLK];
    __shared__ bool  last;

    int g = blockIdx.x, b = blockIdx.y, tid = threadIdx.x;
    int lane = tid & 31, warp = tid >> 5;
    size_t base = (size_t)g * CHUNK + (size_t)tid * CPT;
    const float4* p0 = (const float4*)(xp + (size_t)(b * 2 + 0) * T_LEN + base);
    const float4* p1 = (const float4*)(xp + (size_t)(b * 2 + 1) * T_LEN + base);
    const float4* q0 = (const float4*)(xt + (size_t)(b * 2 + 0) * T_LEN + base);
    const float4* q1 = (const float4*)(xt + (size_t)(b * 2 + 1) * T_LEN + base);

    // ── Phase A: read input ONCE, quantize v to half2 (cached in smem), run 24 chains ──
    float y[24];
#pragma unroll
    for (int c = 0; c < 24; c++) y[c] = 0.0f;

#pragma unroll
    for (int jj = 0; jj < CPT / 4; jj++) {
        float4 a0 = p0[jj], a1 = p1[jj], b0 = q0[jj], b1 = q1[jj];
#define PH_A(e, el) {                                                            \
        float sm = a0.e + a1.e, sd = a0.e - a1.e;                                \
        float tm = b0.e + b1.e, td = b0.e - b1.e;                                \
        __half2 va = __floats2half2_rn(fmaxf(0.5f * sm * sm, HMIN),              \
                                       fmaxf(0.5f * tm * tm, HMIN));             \
        __half2 vb = __floats2half2_rn(fmaxf(0.5f * sd * sd, HMIN),              \
                                       fmaxf(0.5f * td * td, HMIN));             \
        sv[(el) * BLK + tid] = h2u(va);                                          \
        sv[CPT * BLK + (el) * BLK + tid] = h2u(vb);                              \
        float2 fa = __half22float2(va), fb = __half22float2(vb);                 \
        chain24(y, K, fa.x, fa.y, fb.x, fb.y); }
        PH_A(x, jj * 4 + 0) PH_A(y, jj * 4 + 1) PH_A(z, jj * 4 + 2) PH_A(w, jj * 4 + 3)
#undef PH_A
    }

    // ── Warp decayed scan over 24 channels ──
    float pw[6];
#pragma unroll
    for (int k = 0; k < 6; k++) pw[k] = K.aC[k];
#pragma unroll
    for (int off = 1; off < 32; off <<= 1) {
#pragma unroll
        for (int c = 0; c < 24; c++) {
            float up = __shfl_up_sync(0xffffffffu, y[c], off);
            if (lane >= off) y[c] = fmaf(pw[c % 6], up, y[c]);
        }
#pragma unroll
        for (int k = 0; k < 6; k++) pw[k] *= pw[k];   // ends at aC^32
    }
    if (lane == 31) {
#pragma unroll
        for (int c = 0; c < 24; c++) wagg[c][warp] = y[c];
    }
    __syncthreads();
    if (tid < 24) {
        float p = 0.0f, aW = pw[tid % 6];
#pragma unroll
        for (int w = 0; w < 8; w++) {
            float t = wagg[tid][w];
            wagg[tid][w] = p;               // exclusive warp prefix
            p = fmaf(aW, p, t);
        }
        tot_s[tid] = p;                     // block total
    }
    __syncthreads();

    // ── Publish local totals ASAP (before any waiting!) ──
    if (tid == 0) {
        float4* dst = (float4*)g_tot[b][g];
#pragma unroll
        for (int q = 0; q < 6; q++) dst[q] = ((float4*)tot_s)[q];
        st_release(&g_flag[b][g], 1);
    }

    // ── Thread-exclusive local prefix (block scope) ──
    float cin[24];
    {
        float alane[6];
        pow_ladder(alane, K.aC, lane + 1);
#pragma unroll
        for (int c = 0; c < 24; c++) {
            float P  = wagg[c][warp];
            float bi = fmaf(alane[c % 6], P, y[c]);        // block-inclusive
            float pr = __shfl_up_sync(0xffffffffu, bi, 1);
            cin[c] = (lane == 0) ? P : pr;
        }
    }

    // ── Phase B: FULL decoupled lookback — carry = sum_d aL^d * local(g-1-d) ──
    float contrib[24];
#pragma unroll
    for (int c = 0; c < 24; c++) contrib[c] = 0.0f;
    if (tid < g) {
        int j = g - 1 - tid;
        float wd[6];
        pow_ladder(wd, K.aL, tid);
        while (!ld_acquire(&g_flag[b][j])) __nanosleep(64);
        const float4* tp = (const float4*)g_tot[b][j];
#pragma unroll
        for (int q = 0; q < 6; q++) {
            float4 v4 = __ldcg(tp + q);
            contrib[q * 4 + 0] = wd[(q * 4 + 0) % 6] * v4.x;
            contrib[q * 4 + 1] = wd[(q * 4 + 1) % 6] * v4.y;
            contrib[q * 4 + 2] = wd[(q * 4 + 2) % 6] * v4.z;
            contrib[q * 4 + 3] = wd[(q * 4 + 3) % 6] * v4.w;
        }
    }
#pragma unroll
    for (int off = 16; off > 0; off >>= 1) {
#pragma unroll
        for (int c = 0; c < 24; c++)
            contrib[c] += __shfl_xor_sync(0xffffffffu, contrib[c], off);
    }
    if (lane == 0) {
#pragma unroll
        for (int c = 0; c < 24; c++) cagg[c][warp] = contrib[c];
    }
    __syncthreads();
    if (tid < 24) {
        float s = 0.0f;
#pragma unroll
        for (int w = 0; w < 8; w++) s += cagg[tid][w];
        cb_s[tid] = s;
    }
    __syncthreads();

    {   // fold chunk carry into per-thread carry-in: cin += aC^tid * carry
        float atid[6];
        pow_ladder(atid, K.aC, tid);
#pragma unroll
        for (int c = 0; c < 24; c++) cin[c] = fmaf(atid[c % 6], cb_s[c], cin[c]);
    }

    // ── Phase C: replay chains from smem-cached v.
    //    A (short) pre-shifted FORWARD to amap(t+sh) -> written by EARLIER-launched
    //    readers' perspective (chunk g's A comes from blocks g-16..g-2).
    //    C (long) at own addr: i=0,1 overwrite the v slots in smem, i=2 to global. ──
    int tbase = g * CHUNK + tid * CPT;
    int abase = g * CHUNK + tid;       // amap(t) = g*4096 + el*256 + tid
    const int sh[3] = {SH0, SH1, SH2};

#pragma unroll
    for (int el = 0; el < CPT; el++) {
        float2 fa = u2f2(sv[el * BLK + tid]);
        float2 fb = u2f2(sv[CPT * BLK + el * BLK + tid]);
        chain24(cin, K, fa.x, fa.y, fb.x, fb.y);
        int t = tbase + el;
        int aad = abase + (el << 8);
#pragma unroll
        for (int i = 0; i < 3; i++) {
            __half2 Av = __floats2half2_rn(__log2f(cin[i])      - __log2f(cin[6 + i]),
                                           __log2f(cin[12 + i]) - __log2f(cin[18 + i]));
            __half2 Cv = __floats2half2_rn(__log2f(cin[3 + i])  - __log2f(cin[9 + i]),
                                           __log2f(cin[15 + i]) - __log2f(cin[21 + i]));
            int t2 = (t + sh[i]) & (T_LEN - 1);
            g_S[b][i][0][amap(t2)] = h2u(Av);                      // A, pre-shifted forward
            if (i < 2) sv[i * (CPT * BLK) + el * BLK + tid] = h2u(Cv);  // C local in smem
            else       g_S[b][2][1][aad] = h2u(Cv);                // C i=2 local, global
        }
    }

    // ── Arrive on the A chunks this block wrote (after ALL stores) ──
    __syncthreads();
    if (tid < 6) {
        __threadfence();
        int i = tid >> 1;
        const int FO[3] = {2, 7, 15};           // floor(sh/4096)
        int c = (g + FO[i] + (tid & 1)) & (NCHUNK - 1);
        atomicAdd(&g_cflag[b][i][c], 1);
    }
    // ── Wait for own A chunk (writers are blocks g-16..g-2: launched earlier) ──
    if (tid < 3) {
        while (ld_acquire(&g_cflag[b][tid][g]) < 2) __nanosleep(64);
    }
    __syncthreads();

    // ── Tail: reduce |A - C| over own chunk. C(i=0,1) from smem, rest global (L2-hot) ──
    float2 acc2 = make_float2(0.0f, 0.0f);
    int base4 = g * (CHUNK / 4);                 // uint4 index of chunk start
#pragma unroll
    for (int i = 0; i < 3; i++) {
        const uint4* A4 = (const uint4*)&g_S[b][i][0][0];
        const uint4* C4 = (const uint4*)&g_S[b][2][1][0];   // used only when i==2
#pragma unroll
        for (int r = 0; r < 4; r++) {
            int idx = base4 + r * BLK + tid;
            uint4 a = __ldcg(A4 + idx);
            uint4 c;
            if (i < 2) {
                int el = 4 * r + (tid >> 6);
                int w  = (4 * tid) & 255;
                c = *(const uint4*)&sv[i * (CPT * BLK) + el * BLK + w];  // LDS.128, conflict-free
            } else {
                c = __ldcg(C4 + idx);
            }
            const __half2* ha = (const __half2*)&a;
            const __half2* hc = (const __half2*)&c;
#pragma unroll
            for (int q = 0; q < 4; q++) {
                __half2 d = __habs2(__hsub2(ha[q], hc[q]));
                float2 fl = __half22float2(d);
                acc2.x += fl.x; acc2.y += fl.y;
            }
        }
    }
    red[tid] = acc2.x + acc2.y;
    __syncthreads();
    for (int s = BLK / 2; s > 0; s >>= 1) {
        if (tid < s) red[tid] += red[tid + s];
        __syncthreads();
    }
    int bid = b * NCHUNK + g;
    if (tid == 0) {
        g_part[bid] = red[0];
        __threadfence();
        unsigned old = atomicAdd(&g_done, 1u);
        last = (old == NBLOCKS - 1);
    }
    __syncthreads();

    // ── Last block: deterministic final reduction + state reset for next replay ──
    if (last) {
        __threadfence();
        float v = 0.0f;
        for (int idx = tid; idx < NBLOCKS; idx += BLK) v += __ldcg(&g_part[idx]);
        red[tid] = v;
        __syncthreads();
        for (int s = BLK / 2; s > 0; s >>= 1) {
            if (tid < s) red[tid] += red[tid + s];
            __syncthreads();
        }
        if (tid == 0) {
            out[0] = (float)((double)red[0] * 0.69314718055994530942 / (8.0 * (double)T_LEN));
            g_done = 0;
        }
        for (int idx = tid; idx < NB * NCHUNK; idx += BLK) ((int*)g_flag)[idx] = 0;
        for (int idx = tid; idx < NB * 3 * NCHUNK; idx += BLK) ((int*)g_cflag)[idx] = 0;
    }
}

extern "C" void kernel_launch(void* const* d_in, const int* in_sizes, int n_in,
                              void* d_out, int out_size) {
    const float* xp = (const float*)d_in[0];
    const float* xt = (const float*)d_in[1];
    (void)in_sizes; (void)n_in; (void)out_size;

    static bool attr_set = false;
    if (!attr_set) {
        cudaFuncSetAttribute(fused_kernel,
                             cudaFuncAttributePreferredSharedMemoryCarveout,
                             cudaSharedmemCarveoutMaxShared);
        attr_set = true;
    }

    Consts K;
    const double sr = 44100.0;
    const double s_taus[3] = {10.0, 50.0, 100.0};
    const double l_taus[3] = {500.0, 1500.0, 3000.0};
    float cco[6];
    for (int i = 0; i < 3; i++) {
        cco[i]     = (float)(1.0 - exp(-2200.0 / (s_taus[i] * sr)));
        cco[3 + i] = (float)(1.0 - exp(-2200.0 / (l_taus[i] * sr)));
    }
    for (int k = 0; k < 6; k++) {
        K.a[k]  = 1.0f - cco[k];
        K.aC[k] = (float)pow((double)K.a[k], (double)CPT);
        K.aL[k] = (float)pow((double)K.a[k], (double)CHUNK);
    }

    dim3 grid(NCHUNK, NB);
    fused_kernel<<<grid, BLK>>>(xp, xt, K, (float*)d_out);
}

// round 17
// speedup vs baseline: 1.4270x; 1.0390x over previous
#include <cuda_runtime.h>
#include <cuda_fp16.h>
#include <math.h>

#define T_LEN  (1 << 20)
#define CPT    16                  // elements per thread
#define BLK    256
#define CHUNK  (BLK * CPT)         // 4096
#define NCHUNK (T_LEN / CHUNK)     // 256
#define NB     4
#define HMIN   6.103515625e-05f    // fp16 min normal clip floor (validated: rel_err 4.4e-5)
#define NBLOCKS (NB * NCHUNK)
// Hardcoded shifts: int(44100*(l_ms-s_ms)*0.0005)
#define SH0 10804
#define SH1 31972
#define SH2 63945

struct Consts {
    float a[6];   // 1 - c   (k 0..2 short, 3..5 long)
    float aC[6];  // a^CPT
    float aL[6];  // a^CHUNK (up to 0.934 for tau=3000ms -> FULL lookback required)
};

// Static device scratch (no cudaMalloc allowed)
__device__ __align__(128) float g_tot[NB][NCHUNK][32];   // chunk-local totals (24 used)
__device__ int      g_flag[NB][NCHUNK];                  // totals published
__device__ int      g_cflag[NB][3][NCHUNK];              // A-chunk write counters (==2 when ready)
// half2 (row0,row1) streams: [b][i][kind 0=A(short, pre-shifted FORWARD) 1=C(long, own addr; only i=2)]
__device__ __align__(16) unsigned g_S[NB][3][2][T_LEN];
__device__ float    g_part[NBLOCKS];
__device__ unsigned g_done;

__device__ __forceinline__ int ld_acquire(const int* p) {
    int v;
    asm volatile("ld.acquire.gpu.b32 %0, [%1];" : "=r"(v) : "l"(p) : "memory");
    return v;
}
__device__ __forceinline__ void st_release(int* p, int v) {
    asm volatile("st.release.gpu.b32 [%0], %1;" :: "l"(p), "r"(v) : "memory");
}
__device__ __forceinline__ unsigned h2u(__half2 h) {
    return *reinterpret_cast<const unsigned*>(&h);
}
__device__ __forceinline__ float2 u2f2(unsigned u) {
    return __half22float2(*reinterpret_cast<const __half2*>(&u));
}
// Within-chunk transpose: amap(t) for t = g*4096 + tid*16 + el is g*4096 + el*256 + tid.
__device__ __forceinline__ int amap(int s) {
    return (s & ~4095) | ((s & 15) << 8) | ((s & 4095) >> 4);
}

// out[k] = base[k]^e via exact squaring ladder (e <= 255)
__device__ __forceinline__ void pow_ladder(float* out, const float* base, int e) {
#pragma unroll
    for (int k = 0; k < 6; k++) {
        float p = 1.0f, bb = base[k];
        int ee = e;
#pragma unroll
        for (int bit = 0; bit < 8; bit++) { if (ee & 1) p *= bb; bb *= bb; ee >>= 1; }
        out[k] = p;
    }
}

// 24 z-chains (c factored out; cancels in log-differences):
// z[0..5]=pred-mid, z[6..11]=true-mid, z[12..17]=pred-side, z[18..23]=true-side
__device__ __forceinline__ void chain24(float* z, const Consts& K,
                                        float vpm, float vtm, float vps, float vts) {
#pragma unroll
    for (int k = 0; k < 6; k++) {
        z[k]      = fmaf(K.a[k], z[k],      vpm);
        z[6 + k]  = fmaf(K.a[k], z[6 + k],  vtm);
        z[12 + k] = fmaf(K.a[k], z[12 + k], vps);
        z[18 + k] = fmaf(K.a[k], z[18 + k], vts);
    }
}

__global__ __launch_bounds__(BLK, 4) void fused_kernel(const float* __restrict__ xp,
                                                       const float* __restrict__ xt, Consts K,
                                                       float* __restrict__ out) {
    // fp16x2 v-cache (32KB): [kind][el][tid]. Phase C overwrites consumed slots with
    // the LONG (C) log-diff for i = kind (0/1); tail reads them back via LDS.
    // C(i=2) and all pre-shifted A go through global.
    __shared__ __align__(16) unsigned sv[2 * CPT * BLK];
    __shared__ float wagg[24][8];                 // exclusive warp prefixes
    __shared__ float cagg[24][8];                 // lookback cross-warp partials
    __shared__ __align__(16) float tot_s[24];     // block totals
    __shared__ float cb_s[24];                    // chunk carry-in
    __shared__ float red[8];                      // cross-warp reduce slots
    __shared__ bool  last;

    int g = blockIdx.x, b = blockIdx.y, tid = threadIdx.x;
    int lane = tid & 31, warp = tid >> 5;
    size_t base = (size_t)g * CHUNK + (size_t)tid * CPT;
    const float4* p0 = (const float4*)(xp + (size_t)(b * 2 + 0) * T_LEN + base);
    const float4* p1 = (const float4*)(xp + (size_t)(b * 2 + 1) * T_LEN + base);
    const float4* q0 = (const float4*)(xt + (size_t)(b * 2 + 0) * T_LEN + base);
    const float4* q1 = (const float4*)(xt + (size_t)(b * 2 + 1) * T_LEN + base);

    // ── Phase A: read input ONCE, quantize v to half2 (cached in smem), run 24 chains ──
    float y[24];
#pragma unroll
    for (int c = 0; c < 24; c++) y[c] = 0.0f;

#pragma unroll
    for (int jj = 0; jj < CPT / 4; jj++) {
        float4 a0 = p0[jj], a1 = p1[jj], b0 = q0[jj], b1 = q1[jj];
#define PH_A(e, el) {                                                            \
        float sm = a0.e + a1.e, sd = a0.e - a1.e;                                \
        float tm = b0.e + b1.e, td = b0.e - b1.e;                                \
        __half2 va = __floats2half2_rn(fmaxf(0.5f * sm * sm, HMIN),              \
                                       fmaxf(0.5f * tm * tm, HMIN));             \
        __half2 vb = __floats2half2_rn(fmaxf(0.5f * sd * sd, HMIN),              \
                                       fmaxf(0.5f * td * td, HMIN));             \
        sv[(el) * BLK + tid] = h2u(va);                                          \
        sv[CPT * BLK + (el) * BLK + tid] = h2u(vb);                              \
        float2 fa = __half22float2(va), fb = __half22float2(vb);                 \
        chain24(y, K, fa.x, fa.y, fb.x, fb.y); }
        PH_A(x, jj * 4 + 0) PH_A(y, jj * 4 + 1) PH_A(z, jj * 4 + 2) PH_A(w, jj * 4 + 3)
#undef PH_A
    }

    // ── Warp decayed scan over 24 channels; capture alane = aC^(lane+1) on the fly ──
    float pw[6], alane[6];
    int el1 = lane + 1;
#pragma unroll
    for (int k = 0; k < 6; k++) { pw[k] = K.aC[k]; alane[k] = 1.0f; }
#pragma unroll
    for (int off = 1; off < 32; off <<= 1) {
#pragma unroll
        for (int k = 0; k < 6; k++) if (el1 & off) alane[k] *= pw[k];
#pragma unroll
        for (int c = 0; c < 24; c++) {
            float up = __shfl_up_sync(0xffffffffu, y[c], off);
            if (lane >= off) y[c] = fmaf(pw[c % 6], up, y[c]);
        }
#pragma unroll
        for (int k = 0; k < 6; k++) pw[k] *= pw[k];   // ends at aC^32
    }
#pragma unroll
    for (int k = 0; k < 6; k++) if (el1 & 32) alane[k] *= pw[k];   // lane==31 only

    if (lane == 31) {
#pragma unroll
        for (int c = 0; c < 24; c++) wagg[c][warp] = y[c];
    }
    __syncthreads();
    if (tid < 24) {
        float p = 0.0f, aW = pw[tid % 6];
#pragma unroll
        for (int w = 0; w < 8; w++) {
            float t = wagg[tid][w];
            wagg[tid][w] = p;               // exclusive warp prefix
            p = fmaf(aW, p, t);
        }
        tot_s[tid] = p;                     // block total
    }
    __syncthreads();

    // ── Publish local totals ASAP (before any waiting!) ──
    if (tid == 0) {
        float4* dst = (float4*)g_tot[b][g];
#pragma unroll
        for (int q = 0; q < 6; q++) dst[q] = ((float4*)tot_s)[q];
        st_release(&g_flag[b][g], 1);
    }

    // ── Thread-exclusive local prefix (block scope) ──
    float cin[24];
#pragma unroll
    for (int c = 0; c < 24; c++) {
        float P  = wagg[c][warp];
        float bi = fmaf(alane[c % 6], P, y[c]);            // block-inclusive
        float pr = __shfl_up_sync(0xffffffffu, bi, 1);
        cin[c] = (lane == 0) ? P : pr;
    }

    // ── Phase B: FULL decoupled lookback — carry = sum_d aL^d * local(g-1-d) ──
    float contrib[24];
#pragma unroll
    for (int c = 0; c < 24; c++) contrib[c] = 0.0f;
    if (tid < g) {
        int j = g - 1 - tid;
        float wd[6];
        pow_ladder(wd, K.aL, tid);
        while (!ld_acquire(&g_flag[b][j])) __nanosleep(64);
        const float4* tp = (const float4*)g_tot[b][j];
#pragma unroll
        for (int q = 0; q < 6; q++) {
            float4 v4 = __ldcg(tp + q);
            contrib[q * 4 + 0] = wd[(q * 4 + 0) % 6] * v4.x;
            contrib[q * 4 + 1] = wd[(q * 4 + 1) % 6] * v4.y;
            contrib[q * 4 + 2] = wd[(q * 4 + 2) % 6] * v4.z;
            contrib[q * 4 + 3] = wd[(q * 4 + 3) % 6] * v4.w;
        }
    }
#pragma unroll
    for (int off = 16; off > 0; off >>= 1) {
#pragma unroll
        for (int c = 0; c < 24; c++)
            contrib[c] += __shfl_xor_sync(0xffffffffu, contrib[c], off);
    }
    if (lane == 0) {
#pragma unroll
        for (int c = 0; c < 24; c++) cagg[c][warp] = contrib[c];
    }
    __syncthreads();
    if (tid < 24) {
        float s = 0.0f;
#pragma unroll
        for (int w = 0; w < 8; w++) s += cagg[tid][w];
        cb_s[tid] = s;
    }
    __syncthreads();

    {   // fold chunk carry into per-thread carry-in: cin += aC^tid * carry
        float atid[6];
        pow_ladder(atid, K.aC, tid);
#pragma unroll
        for (int c = 0; c < 24; c++) cin[c] = fmaf(atid[c % 6], cb_s[c], cin[c]);
    }

    // ── Phase C: replay chains from smem-cached v.
    //    A (short) pre-shifted FORWARD to amap(t+sh): chunk g's A comes from blocks g-16..g-2.
    //    C (long) at own addr: i=0,1 overwrite the v slots in smem, i=2 to global. ──
    int tbase = g * CHUNK + tid * CPT;
    int abase = g * CHUNK + tid;       // amap(t) = g*4096 + el*256 + tid
    const int sh[3] = {SH0, SH1, SH2};

#pragma unroll
    for (int el = 0; el < CPT; el++) {
        float2 fa = u2f2(sv[el * BLK + tid]);
        float2 fb = u2f2(sv[CPT * BLK + el * BLK + tid]);
        chain24(cin, K, fa.x, fa.y, fb.x, fb.y);
        int t = tbase + el;
        int aad = abase + (el << 8);
#pragma unroll
        for (int i = 0; i < 3; i++) {
            __half2 Av = __floats2half2_rn(__log2f(cin[i])      - __log2f(cin[6 + i]),
                                           __log2f(cin[12 + i]) - __log2f(cin[18 + i]));
            __half2 Cv = __floats2half2_rn(__log2f(cin[3 + i])  - __log2f(cin[9 + i]),
                                           __log2f(cin[15 + i]) - __log2f(cin[21 + i]));
            int t2 = (t + sh[i]) & (T_LEN - 1);
            g_S[b][i][0][amap(t2)] = h2u(Av);                      // A, pre-shifted forward
            if (i < 2) sv[i * (CPT * BLK) + el * BLK + tid] = h2u(Cv);  // C local in smem
            else       g_S[b][2][1][aad] = h2u(Cv);                // C i=2 local, global
        }
    }

    // ── Arrive on the A chunks this block wrote (after ALL stores) ──
    __syncthreads();
    if (tid < 6) {
        __threadfence();
        int i = tid >> 1;
        const int FO[3] = {2, 7, 15};           // floor(sh/4096)
        int c = (g + FO[i] + (tid & 1)) & (NCHUNK - 1);
        atomicAdd(&g_cflag[b][i][c], 1);
    }
    // ── Wait for own A chunk (writers are blocks g-16..g-2: launched earlier) ──
    if (tid < 3) {
        while (ld_acquire(&g_cflag[b][tid][g]) < 2) __nanosleep(64);
    }
    __syncthreads();

    // ── Tail: reduce |A - C| over own chunk. C(i=0,1) from smem, rest global (L2-hot) ──
    float accf = 0.0f;
    int base4 = g * (CHUNK / 4);                 // uint4 index of chunk start
#pragma unroll
    for (int i = 0; i < 3; i++) {
        const uint4* A4 = (const uint4*)&g_S[b][i][0][0];
        const uint4* C4 = (const uint4*)&g_S[b][2][1][0];   // used only when i==2
#pragma unroll
        for (int r = 0; r < 4; r++) {
            int idx = base4 + r * BLK + tid;
            uint4 a = __ldcg(A4 + idx);
            uint4 c;
            if (i < 2) {
                int el = 4 * r + (tid >> 6);
                int w  = (4 * tid) & 255;
                c = *(const uint4*)&sv[i * (CPT * BLK) + el * BLK + w];  // LDS.128, conflict-free
            } else {
                c = __ldcg(C4 + idx);
            }
            const __half2* ha = (const __half2*)&a;
            const __half2* hc = (const __half2*)&c;
            // pair-accumulate 8 halves in half2 (sums <= ~4 per half: RN noise negligible)
            __half2 s01 = __hadd2(__habs2(__hsub2(ha[0], hc[0])),
                                  __habs2(__hsub2(ha[1], hc[1])));
            __half2 s23 = __hadd2(__habs2(__hsub2(ha[2], hc[2])),
                                  __habs2(__hsub2(ha[3], hc[3])));
            float2 fl = __half22float2(__hadd2(s01, s23));
            accf += fl.x + fl.y;
        }
    }
    // warp butterfly + cross-warp (deterministic fixed order)
#pragma unroll
    for (int off = 16; off > 0; off >>= 1)
        accf += __shfl_xor_sync(0xffffffffu, accf, off);
    if (lane == 0) red[warp] = accf;
    __syncthreads();
    int bid = b * NCHUNK + g;
    if (tid == 0) {
        float s = 0.0f;
#pragma unroll
        for (int w = 0; w < 8; w++) s += red[w];
        g_part[bid] = s;
        __threadfence();
        unsigned old = atomicAdd(&g_done, 1u);
        last = (old == NBLOCKS - 1);
    }
    __syncthreads();

    // ── Last block: deterministic final reduction + state reset for next replay ──
    if (last) {
        __threadfence();
        float v = 0.0f;
        for (int idx = tid; idx < NBLOCKS; idx += BLK) v += __ldcg(&g_part[idx]);
#pragma unroll
        for (int off = 16; off > 0; off >>= 1)
            v += __shfl_xor_sync(0xffffffffu, v, off);
        if (lane == 0) red[warp] = v;
        __syncthreads();
        if (tid == 0) {
            float s = 0.0f;
#pragma unroll
            for (int w = 0; w < 8; w++) s += red[w];
            out[0] = (float)((double)s * 0.69314718055994530942 / (8.0 * (double)T_LEN));
            g_done = 0;
        }
        for (int idx = tid; idx < NB * NCHUNK; idx += BLK) ((int*)g_flag)[idx] = 0;
        for (int idx = tid; idx < NB * 3 * NCHUNK; idx += BLK) ((int*)g_cflag)[idx] = 0;
    }
}

extern "C" void kernel_launch(void* const* d_in, const int* in_sizes, int n_in,
                              void* d_out, int out_size) {
    const float* xp = (const float*)d_in[0];
    const float* xt = (const float*)d_in[1];
    (void)in_sizes; (void)n_in; (void)out_size;

    static bool attr_set = false;
    if (!attr_set) {
        cudaFuncSetAttribute(fused_kernel,
                             cudaFuncAttributePreferredSharedMemoryCarveout,
                             cudaSharedmemCarveoutMaxShared);
        attr_set = true;
    }

    Consts K;
    const double sr = 44100.0;
    const double s_taus[3] = {10.0, 50.0, 100.0};
    const double l_taus[3] = {500.0, 1500.0, 3000.0};
    float cco[6];
    for (int i = 0; i < 3; i++) {
        cco[i]     = (float)(1.0 - exp(-2200.0 / (s_taus[i] * sr)));
        cco[3 + i] = (float)(1.0 - exp(-2200.0 / (l_taus[i] * sr)));
    }
    for (int k = 0; k < 6; k++) {
        K.a[k]  = 1.0f - cco[k];
        K.aC[k] = (float)pow((double)K.a[k], (double)CPT);
        K.aL[k] = (float)pow((double)K.a[k], (double)CHUNK);
    }

    dim3 grid(NCHUNK, NB);
    fused_kernel<<<grid, BLK>>>(xp, xt, K, (float*)d_out);
}